// round 1
// baseline (speedup 1.0000x reference)
#include <cuda_runtime.h>
#include <stdint.h>

// Problem constants
#define BATCH 1024
#define NA    10
#define NE    11
#define AF    32
#define EF    28
#define HYP   64
#define OUTD  256

// Concatenated-K layout for the single fused GEMM:
//   [0,2048)        M_ally[k*32+f]
//   [2048,2080)     xsum_ally[f]          (bias term via ba2)
//   [2080,3872)     M_enemy[k*28+f]
//   [3872,3900)     xsum_enemy[f]         (bias term via be2)
//   [3900,3904)     zero pad
#define KA      (HYP*AF)        // 2048
#define OFF_FA  KA              // 2048
#define OFF_ME  (KA+AF)         // 2080
#define KE      (HYP*EF)        // 1792
#define OFF_FE  (OFF_ME+KE)     // 3872
#define KTOT    (OFF_FE+EF)     // 3900
#define KP      3904            // padded K (multiple of 32)

// Scratch (no cudaMalloc allowed)
__device__ float g_U[BATCH * KP];          // 16 MB: per-batch reduced features
__device__ float g_Wc[KP * OUTD];          // 4 MB: packed combined weight
__device__ float g_P[2 * BATCH * OUTD];    // 2 MB: split-K partials

// ---------------------------------------------------------------------------
// Kernel 1: pack combined weight matrix Wc[KP][256] from wa2/ba2/we2/be2.
// Row r < 2048 maps directly onto wa2 viewed flat as [2048][256] (layout
// identity: wa2[k][f*256+o] == flat[(k*32+f)*256+o]).
// ---------------------------------------------------------------------------
__global__ void pack_wc(const float* __restrict__ wa2, const float* __restrict__ ba2,
                        const float* __restrict__ we2, const float* __restrict__ be2) {
    int total = KP * OUTD;
    for (int i = blockIdx.x * blockDim.x + threadIdx.x; i < total;
         i += gridDim.x * blockDim.x) {
        int r = i >> 8;        // / 256
        float v;
        if (r < KA)            v = wa2[i];
        else if (r < OFF_ME)   v = ba2[i - KA * OUTD];
        else if (r < OFF_FE)   v = we2[i - OFF_ME * OUTD];
        else if (r < KTOT)     v = be2[i - OFF_FE * OUTD];
        else                   v = 0.0f;
        g_Wc[i] = v;
    }
}

// ---------------------------------------------------------------------------
// Kernel 2: per-batch-element reduced features.
// One block per batch element b:
//   h_a[n][k] = relu(x_a[n] @ wa1 + ba1)   (10x64)
//   h_e[n][k] = relu(x_e[n] @ we1 + be1)   (11x64)
//   U[b] = [ sum_n h_a ⊗ x_a | sum_n x_a | sum_n h_e ⊗ x_e | sum_n x_e | 0 ]
// ---------------------------------------------------------------------------
__global__ __launch_bounds__(256) void build_u(
    const float* __restrict__ fa, const float* __restrict__ fe,
    const float* __restrict__ wa1, const float* __restrict__ ba1,
    const float* __restrict__ we1, const float* __restrict__ be1) {

    __shared__ float s_wa1[AF * HYP];   // [f][k] row-major, as stored
    __shared__ float s_we1[EF * HYP];
    __shared__ float s_fa[NA][AF];
    __shared__ float s_fe[NE][EF];
    __shared__ float s_ha[NA][HYP];
    __shared__ float s_he[NE][HYP];

    const int b = blockIdx.x;
    const int t = threadIdx.x;

    for (int i = t; i < AF * HYP; i += 256) s_wa1[i] = wa1[i];
    for (int i = t; i < EF * HYP; i += 256) s_we1[i] = we1[i];
    for (int i = t; i < NA * AF; i += 256) s_fa[i / AF][i % AF] = fa[b * NA * AF + i];
    for (int i = t; i < NE * EF; i += 256) s_fe[i / EF][i % EF] = fe[b * NE * EF + i];
    __syncthreads();

    // hypernet hidden layers
    for (int i = t; i < NA * HYP; i += 256) {
        int n = i / HYP, k = i % HYP;
        float s = ba1[k];
        #pragma unroll
        for (int f = 0; f < AF; f++) s += s_fa[n][f] * s_wa1[f * HYP + k];
        s_ha[n][k] = fmaxf(s, 0.0f);
    }
    for (int i = t; i < NE * HYP; i += 256) {
        int n = i / HYP, k = i % HYP;
        float s = be1[k];
        #pragma unroll
        for (int f = 0; f < EF; f++) s += s_fe[n][f] * s_we1[f * HYP + k];
        s_he[n][k] = fmaxf(s, 0.0f);
    }
    __syncthreads();

    float* Urow = g_U + (size_t)b * KP;

    // ally outer products summed over entities
    for (int i = t; i < KA; i += 256) {
        int k = i >> 5, f = i & 31;
        float s = 0.0f;
        #pragma unroll
        for (int n = 0; n < NA; n++) s += s_ha[n][k] * s_fa[n][f];
        Urow[i] = s;
    }
    if (t < AF) {
        float s = 0.0f;
        #pragma unroll
        for (int n = 0; n < NA; n++) s += s_fa[n][t];
        Urow[OFF_FA + t] = s;
    }
    // enemy outer products
    for (int i = t; i < KE; i += 256) {
        int k = i / EF, f = i - k * EF;
        float s = 0.0f;
        #pragma unroll
        for (int n = 0; n < NE; n++) s += s_he[n][k] * s_fe[n][f];
        Urow[OFF_ME + i] = s;
    }
    if (t < EF) {
        float s = 0.0f;
        #pragma unroll
        for (int n = 0; n < NE; n++) s += s_fe[n][t];
        Urow[OFF_FE + t] = s;
    }
    if (t < (KP - KTOT)) Urow[KTOT + t] = 0.0f;   // zero pad
}

// ---------------------------------------------------------------------------
// Kernel 3: GEMM  P[z] += U[:, Kz] @ Wc[Kz, :]   (split-K = 2, deterministic)
// 32x32 block tile, 64 threads, 4x4 micro-tile, BK=32.
// grid = (1024/32, 256/32, 2) = (32, 8, 2) = 512 blocks.
// ---------------------------------------------------------------------------
#define BK 32

__global__ __launch_bounds__(64) void gemm_split() {
    __shared__ float As[BK][36];   // [k][m], stride 36 keeps float4 LDS aligned
    __shared__ float Bs[BK][32];   // [k][n]

    const int t  = threadIdx.x;
    const int tx = t & 7;          // 0..7  -> 4 output cols each
    const int ty = t >> 3;         // 0..7  -> 4 output rows each
    const int m0 = blockIdx.x * 32;
    const int n0 = blockIdx.y * 32;
    const int kz0 = blockIdx.z * (KP / 2);
    const int kz1 = kz0 + (KP / 2);

    float acc[4][4] = {};

    for (int k0 = kz0; k0 < kz1; k0 += BK) {
        // stage tiles: 256 float4 loads per tile pair, 4 per thread
        #pragma unroll
        for (int i = t; i < 256; i += 64) {
            int lr = i >> 3;
            int lc = (i & 7) * 4;
            float4 av = *(const float4*)(g_U + (size_t)(m0 + lr) * KP + k0 + lc);
            As[lc + 0][lr] = av.x;
            As[lc + 1][lr] = av.y;
            As[lc + 2][lr] = av.z;
            As[lc + 3][lr] = av.w;
            float4 bv = *(const float4*)(g_Wc + (size_t)(k0 + lr) * OUTD + n0 + lc);
            *(float4*)&Bs[lr][lc] = bv;
        }
        __syncthreads();

        #pragma unroll
        for (int kk = 0; kk < BK; kk++) {
            float4 a = *(const float4*)&As[kk][4 * ty];
            float4 bq = *(const float4*)&Bs[kk][4 * tx];
            float av4[4] = {a.x, a.y, a.z, a.w};
            float bv4[4] = {bq.x, bq.y, bq.z, bq.w};
            #pragma unroll
            for (int i = 0; i < 4; i++)
                #pragma unroll
                for (int j = 0; j < 4; j++)
                    acc[i][j] += av4[i] * bv4[j];
        }
        __syncthreads();
    }

    float* P = g_P + (size_t)blockIdx.z * (BATCH * OUTD);
    #pragma unroll
    for (int i = 0; i < 4; i++) {
        float4 v = make_float4(acc[i][0], acc[i][1], acc[i][2], acc[i][3]);
        *(float4*)(P + (size_t)(m0 + 4 * ty + i) * OUTD + n0 + 4 * tx) = v;
    }
}

// ---------------------------------------------------------------------------
// Kernel 4: reduce the two split-K partials into d_out.
// ---------------------------------------------------------------------------
__global__ void reduce_out(float* __restrict__ out) {
    int i = blockIdx.x * blockDim.x + threadIdx.x;
    if (i < BATCH * OUTD) out[i] = g_P[i] + g_P[BATCH * OUTD + i];
}

// ---------------------------------------------------------------------------
// Input order (reference signature):
//  0 ally_features [10240,32]   1 enemy_features [11264,28]
//  2 wa1 [32,64]  3 ba1 [64]  4 wa2 [64,8192]  5 ba2 [8192]
//  6 we1 [28,64]  7 be1 [64]  8 we2 [64,7168]  9 be2 [7168]
// output: float32 [1024,256]
// ---------------------------------------------------------------------------
extern "C" void kernel_launch(void* const* d_in, const int* in_sizes, int n_in,
                              void* d_out, int out_size) {
    const float* fa  = (const float*)d_in[0];
    const float* fe  = (const float*)d_in[1];
    const float* wa1 = (const float*)d_in[2];
    const float* ba1 = (const float*)d_in[3];
    const float* wa2 = (const float*)d_in[4];
    const float* ba2 = (const float*)d_in[5];
    const float* we1 = (const float*)d_in[6];
    const float* be1 = (const float*)d_in[7];
    const float* we2 = (const float*)d_in[8];
    const float* be2 = (const float*)d_in[9];
    float* out = (float*)d_out;

    pack_wc<<<512, 256>>>(wa2, ba2, we2, be2);
    build_u<<<BATCH, 256>>>(fa, fe, wa1, ba1, we1, be1);
    gemm_split<<<dim3(BATCH / 32, OUTD / 32, 2), 64>>>();
    reduce_out<<<(BATCH * OUTD + 255) / 256, 256>>>(out);
}

// round 2
// speedup vs baseline: 1.4459x; 1.4459x over previous
#include <cuda_runtime.h>
#include <stdint.h>

typedef unsigned long long ull;

// Problem constants
#define BATCH 1024
#define NA    10
#define NE    11
#define AF    32
#define EF    28
#define HYP   64
#define OUTD  256

// Concatenated-K layout for the single fused GEMM:
//   [0,2048)        M_ally[k*32+f]
//   [2048,2080)     xsum_ally[f]          (bias term via ba2)
//   [2080,3872)     M_enemy[k*28+f]
//   [3872,3900)     xsum_enemy[f]         (bias term via be2)
//   [3900,3904)     zero pad
#define KA      (HYP*AF)        // 2048
#define OFF_FA  KA              // 2048
#define OFF_ME  (KA+AF)         // 2080
#define KE      (HYP*EF)        // 1792
#define OFF_FE  (OFF_ME+KE)     // 3872
#define KTOT    (OFF_FE+EF)     // 3900
#define KP      3904            // padded K (61 * 64)

#define SPLITK  8
#define BM      64
#define BN      64
#define BKK     16
#define NSLABS  (KP / BKK)      // 244
#define ASTR    68              // padded As row stride (floats); 272B, 16B aligned

// Scratch (no cudaMalloc allowed)
__device__ float g_U[BATCH * KP];                 // 16 MB
__device__ float g_Wc[KP * OUTD];                 // 4 MB
__device__ float g_P[SPLITK * BATCH * OUTD];      // 8 MB split-K partials

__device__ __forceinline__ void fma2(ull& d, ull a, ull b) {
    asm("fma.rn.f32x2 %0, %1, %2, %0;" : "+l"(d) : "l"(a), "l"(b));
}
__device__ __forceinline__ ull pack2(float x) {
    ull r; asm("mov.b64 %0, {%1, %2};" : "=l"(r) : "f"(x), "f"(x)); return r;
}
__device__ __forceinline__ void unpack2(ull d, float& lo, float& hi) {
    asm("mov.b64 {%0, %1}, %2;" : "=f"(lo), "=f"(hi) : "l"(d));
}

// ---------------------------------------------------------------------------
// Kernel 1: pack combined weight matrix Wc[KP][256].
// wa2 flat [2048][256] row-major IS W'[(k*32+f)][o] — direct copy.
// ---------------------------------------------------------------------------
__global__ void pack_wc(const float* __restrict__ wa2, const float* __restrict__ ba2,
                        const float* __restrict__ we2, const float* __restrict__ be2) {
    int total = KP * OUTD;
    for (int i = blockIdx.x * blockDim.x + threadIdx.x; i < total;
         i += gridDim.x * blockDim.x) {
        int r = i >> 8;
        float v;
        if (r < KA)            v = wa2[i];
        else if (r < OFF_ME)   v = ba2[i - KA * OUTD];
        else if (r < OFF_FE)   v = we2[i - OFF_ME * OUTD];
        else if (r < KTOT)     v = be2[i - OFF_FE * OUTD];
        else                   v = 0.0f;
        g_Wc[i] = v;
    }
}

// ---------------------------------------------------------------------------
// Kernel 2: per-batch reduced features (hypernet hidden + entity-summed outer
// products). One block per batch element.
// ---------------------------------------------------------------------------
__global__ __launch_bounds__(256) void build_u(
    const float* __restrict__ fa, const float* __restrict__ fe,
    const float* __restrict__ wa1, const float* __restrict__ ba1,
    const float* __restrict__ we1, const float* __restrict__ be1) {

    __shared__ float s_wa1[AF * HYP];
    __shared__ float s_we1[EF * HYP];
    __shared__ float s_fa[NA][AF];
    __shared__ float s_fe[NE][EF];
    __shared__ float s_ha[NA][HYP];
    __shared__ float s_he[NE][HYP];

    const int b = blockIdx.x;
    const int t = threadIdx.x;

    for (int i = t; i < AF * HYP; i += 256) s_wa1[i] = wa1[i];
    for (int i = t; i < EF * HYP; i += 256) s_we1[i] = we1[i];
    for (int i = t; i < NA * AF; i += 256) s_fa[i / AF][i % AF] = fa[b * NA * AF + i];
    for (int i = t; i < NE * EF; i += 256) s_fe[i / EF][i % EF] = fe[b * NE * EF + i];
    __syncthreads();

    for (int i = t; i < NA * HYP; i += 256) {
        int n = i / HYP, k = i % HYP;
        float s = ba1[k];
        #pragma unroll
        for (int f = 0; f < AF; f++) s += s_fa[n][f] * s_wa1[f * HYP + k];
        s_ha[n][k] = fmaxf(s, 0.0f);
    }
    for (int i = t; i < NE * HYP; i += 256) {
        int n = i / HYP, k = i % HYP;
        float s = be1[k];
        #pragma unroll
        for (int f = 0; f < EF; f++) s += s_fe[n][f] * s_we1[f * HYP + k];
        s_he[n][k] = fmaxf(s, 0.0f);
    }
    __syncthreads();

    float* Urow = g_U + (size_t)b * KP;

    for (int i = t; i < KA; i += 256) {
        int k = i >> 5, f = i & 31;
        float s = 0.0f;
        #pragma unroll
        for (int n = 0; n < NA; n++) s += s_ha[n][k] * s_fa[n][f];
        Urow[i] = s;
    }
    if (t < AF) {
        float s = 0.0f;
        #pragma unroll
        for (int n = 0; n < NA; n++) s += s_fa[n][t];
        Urow[OFF_FA + t] = s;
    }
    for (int i = t; i < KE; i += 256) {
        int k = i / EF, f = i - k * EF;
        float s = 0.0f;
        #pragma unroll
        for (int n = 0; n < NE; n++) s += s_he[n][k] * s_fe[n][f];
        Urow[OFF_ME + i] = s;
    }
    if (t < EF) {
        float s = 0.0f;
        #pragma unroll
        for (int n = 0; n < NE; n++) s += s_fe[n][t];
        Urow[OFF_FE + t] = s;
    }
    if (t < (KP - KTOT)) Urow[KTOT + t] = 0.0f;
}

// ---------------------------------------------------------------------------
// Kernel 3: fp32x2 GEMM  P[z] = U[:, Kz] @ Wc[Kz, :]
// 64x64 block tile, 64 threads, 8x8 micro-tile, f32x2-packed along M.
// grid = (16, 4, SPLITK) = 512 blocks.
// ---------------------------------------------------------------------------
__global__ __launch_bounds__(64) void gemm2() {
    __shared__ float As[BKK][ASTR];   // [k][m] transposed, padded
    __shared__ float Bs[BKK][BN];     // [k][n]

    const int t  = threadIdx.x;
    const int tx = t & 7;            // n group: cols 8*tx .. 8*tx+7
    const int ty = t >> 3;           // m group: rows 8*ty .. 8*ty+7
    const int m0 = blockIdx.x * BM;
    const int n0 = blockIdx.y * BN;
    const int s0 = (NSLABS * blockIdx.z) / SPLITK;
    const int s1 = (NSLABS * (blockIdx.z + 1)) / SPLITK;

    ull acc[4][8];
    #pragma unroll
    for (int p = 0; p < 4; p++)
        #pragma unroll
        for (int j = 0; j < 8; j++) acc[p][j] = 0ull;

    for (int s = s0; s < s1; s++) {
        const int k0 = s * BKK;
        // stage A (64m x 16k), transposing into As[k][m]
        #pragma unroll
        for (int q = 0; q < 4; q++) {
            int i = t + q * 64;
            int m  = i >> 2;
            int kq = (i & 3) * 4;
            float4 v = *(const float4*)(g_U + (size_t)(m0 + m) * KP + k0 + kq);
            As[kq + 0][m] = v.x;
            As[kq + 1][m] = v.y;
            As[kq + 2][m] = v.z;
            As[kq + 3][m] = v.w;
        }
        // stage B (16k x 64n), layout-preserving
        #pragma unroll
        for (int q = 0; q < 4; q++) {
            int i = t + q * 64;
            int r = i >> 4;
            int c = (i & 15) * 4;
            *(float4*)&Bs[r][c] = *(const float4*)(g_Wc + (size_t)(k0 + r) * OUTD + n0 + c);
        }
        __syncthreads();

        #pragma unroll
        for (int kk = 0; kk < BKK; kk++) {
            ulonglong2 a01 = *(const ulonglong2*)&As[kk][8 * ty];
            ulonglong2 a23 = *(const ulonglong2*)&As[kk][8 * ty + 4];
            ull a[4] = {a01.x, a01.y, a23.x, a23.y};
            float4 b0 = *(const float4*)&Bs[kk][8 * tx];
            float4 b1 = *(const float4*)&Bs[kk][8 * tx + 4];
            ull bd[8] = {pack2(b0.x), pack2(b0.y), pack2(b0.z), pack2(b0.w),
                         pack2(b1.x), pack2(b1.y), pack2(b1.z), pack2(b1.w)};
            #pragma unroll
            for (int p = 0; p < 4; p++)
                #pragma unroll
                for (int j = 0; j < 8; j++)
                    fma2(acc[p][j], a[p], bd[j]);
        }
        __syncthreads();
    }

    float* P = g_P + (size_t)blockIdx.z * (BATCH * OUTD);
    #pragma unroll
    for (int p = 0; p < 4; p++) {
        float lo[8], hi[8];
        #pragma unroll
        for (int j = 0; j < 8; j++) unpack2(acc[p][j], lo[j], hi[j]);
        size_t r0 = (size_t)(m0 + 8 * ty + 2 * p) * OUTD + n0 + 8 * tx;
        *(float4*)(P + r0)            = make_float4(lo[0], lo[1], lo[2], lo[3]);
        *(float4*)(P + r0 + 4)        = make_float4(lo[4], lo[5], lo[6], lo[7]);
        *(float4*)(P + r0 + OUTD)     = make_float4(hi[0], hi[1], hi[2], hi[3]);
        *(float4*)(P + r0 + OUTD + 4) = make_float4(hi[4], hi[5], hi[6], hi[7]);
    }
}

// ---------------------------------------------------------------------------
// Kernel 4: reduce SPLITK partials into d_out (vectorized).
// ---------------------------------------------------------------------------
__global__ __launch_bounds__(256) void reduce_out(float* __restrict__ out) {
    const int nvec = BATCH * OUTD / 4;
    for (int i = blockIdx.x * blockDim.x + threadIdx.x; i < nvec;
         i += gridDim.x * blockDim.x) {
        float4 s = ((const float4*)g_P)[i];
        #pragma unroll
        for (int z = 1; z < SPLITK; z++) {
            float4 v = ((const float4*)g_P)[(size_t)z * nvec + i];
            s.x += v.x; s.y += v.y; s.z += v.z; s.w += v.w;
        }
        ((float4*)out)[i] = s;
    }
}

// ---------------------------------------------------------------------------
// Inputs (metadata order):
//  0 ally_features  1 enemy_features
//  2 wa1  3 ba1  4 wa2  5 ba2  6 we1  7 be1  8 we2  9 be2
// output: float32 [1024,256]
// ---------------------------------------------------------------------------
extern "C" void kernel_launch(void* const* d_in, const int* in_sizes, int n_in,
                              void* d_out, int out_size) {
    const float* fa  = (const float*)d_in[0];
    const float* fe  = (const float*)d_in[1];
    const float* wa1 = (const float*)d_in[2];
    const float* ba1 = (const float*)d_in[3];
    const float* wa2 = (const float*)d_in[4];
    const float* ba2 = (const float*)d_in[5];
    const float* we1 = (const float*)d_in[6];
    const float* be1 = (const float*)d_in[7];
    const float* we2 = (const float*)d_in[8];
    const float* be2 = (const float*)d_in[9];
    float* out = (float*)d_out;

    pack_wc<<<512, 256>>>(wa2, ba2, we2, be2);
    build_u<<<BATCH, 256>>>(fa, fe, wa1, ba1, we1, be1);
    gemm2<<<dim3(BATCH / BM, OUTD / BN, SPLITK), 64>>>();
    reduce_out<<<128, 256>>>(out);
}

// round 5
// speedup vs baseline: 2.2044x; 1.5247x over previous
#include <cuda_runtime.h>
#include <cuda_bf16.h>
#include <stdint.h>

// Problem constants
#define BATCH 1024
#define NA    10
#define NE    11
#define AF    32
#define EF    28
#define HYP   64
#define OUTD  256

// Concatenated-K layout:
//   [0,2048) M_ally  [2048,2080) xsum_ally  [2080,3872) M_enemy
//   [3872,3900) xsum_enemy  [3900,3904) pad
#define KA      (HYP*AF)
#define OFF_FA  KA
#define OFF_ME  (KA+AF)
#define KE      (HYP*EF)
#define OFF_FE  (OFF_ME+KE)
#define KTOT    (OFF_FE+EF)
#define KP      3904
#define SPLIT   8
#define NST     (KP/32)        // 122 BK=32 stages

// Split-precision operands (hi + lo bf16 ≈ fp32 to ~2^-17)
__device__ __align__(16) __nv_bfloat16 g_Ua_hi[BATCH * KP];   // A  [m][k]
__device__ __align__(16) __nv_bfloat16 g_Ua_lo[BATCH * KP];
__device__ __align__(16) __nv_bfloat16 g_Wt_hi[OUTD * KP];    // B^T [n][k]
__device__ __align__(16) __nv_bfloat16 g_Wt_lo[OUTD * KP];
__device__ float g_P[SPLIT * BATCH * OUTD];                   // split-K partials

// ---------------------------------------------------------------------------
// helpers
// ---------------------------------------------------------------------------
__device__ __forceinline__ uint32_t smem_u32(const void* p) {
    uint32_t a;
    asm("{ .reg .u64 t; cvta.to.shared.u64 t, %1; cvt.u32.u64 %0, t; }" : "=r"(a) : "l"(p));
    return a;
}
__device__ __forceinline__ void cp16(uint32_t dst, const void* src) {
    asm volatile("cp.async.cg.shared.global [%0], [%1], 16;" :: "r"(dst), "l"(src));
}
#define CP_COMMIT() asm volatile("cp.async.commit_group;" ::: "memory")
#define CP_WAIT(N)  asm volatile("cp.async.wait_group %0;" :: "n"(N) : "memory")

__device__ __forceinline__ void ldsm4(uint32_t& r0, uint32_t& r1, uint32_t& r2,
                                      uint32_t& r3, uint32_t addr) {
    asm volatile("ldmatrix.sync.aligned.m8n8.x4.shared.b16 {%0,%1,%2,%3}, [%4];"
                 : "=r"(r0), "=r"(r1), "=r"(r2), "=r"(r3) : "r"(addr));
}
__device__ __forceinline__ void mma_bf16(float* c, const uint32_t* a, const uint32_t* b) {
    asm volatile(
        "mma.sync.aligned.m16n8k16.row.col.f32.bf16.bf16.f32 "
        "{%0,%1,%2,%3},{%4,%5,%6,%7},{%8,%9},{%0,%1,%2,%3};"
        : "+f"(c[0]), "+f"(c[1]), "+f"(c[2]), "+f"(c[3])
        : "r"(a[0]), "r"(a[1]), "r"(a[2]), "r"(a[3]), "r"(b[0]), "r"(b[1]));
}

__device__ __forceinline__ void store_hilo(__nv_bfloat16* ha, __nv_bfloat16* la,
                                           size_t idx, float v) {
    __nv_bfloat16 h = __float2bfloat16(v);
    ha[idx] = h;
    la[idx] = __float2bfloat16(v - __bfloat162float(h));
}

// ---------------------------------------------------------------------------
// Kernel 1: transpose + convert combined weight into Wt[n][k] bf16 hi/lo.
// ---------------------------------------------------------------------------
__global__ __launch_bounds__(256) void pack_t(
    const float* __restrict__ wa2, const float* __restrict__ ba2,
    const float* __restrict__ we2, const float* __restrict__ be2) {
    __shared__ float s[64][65];
    const int t = threadIdx.x;
    const int k0 = blockIdx.x * 64;
    const int n0 = blockIdx.y * 64;

    for (int i = t; i < 64 * 64; i += 256) {
        int kl = i >> 6, nl = i & 63;
        int r = k0 + kl, n = n0 + nl;
        float v;
        if (r < KA)            v = wa2[(size_t)r * OUTD + n];
        else if (r < OFF_ME)   v = ba2[(size_t)(r - KA) * OUTD + n];
        else if (r < OFF_FE)   v = we2[(size_t)(r - OFF_ME) * OUTD + n];
        else if (r < KTOT)     v = be2[(size_t)(r - OFF_FE) * OUTD + n];
        else                   v = 0.0f;
        s[kl][nl] = v;
    }
    __syncthreads();
    for (int i = t; i < 64 * 64; i += 256) {
        int nl = i >> 6, kl = i & 63;
        store_hilo(g_Wt_hi, g_Wt_lo, (size_t)(n0 + nl) * KP + k0 + kl, s[kl][nl]);
    }
}

// ---------------------------------------------------------------------------
// Kernel 2: per-batch reduced features -> U hi/lo bf16.
// ---------------------------------------------------------------------------
__global__ __launch_bounds__(256) void build_u(
    const float* __restrict__ fa, const float* __restrict__ fe,
    const float* __restrict__ wa1, const float* __restrict__ ba1,
    const float* __restrict__ we1, const float* __restrict__ be1) {

    __shared__ float s_wa1[AF * HYP];
    __shared__ float s_we1[EF * HYP];
    __shared__ float s_fa[NA][AF];
    __shared__ float s_fe[NE][EF];
    __shared__ float s_ha[NA][HYP];
    __shared__ float s_he[NE][HYP];

    const int b = blockIdx.x;
    const int t = threadIdx.x;
    const size_t rb = (size_t)b * KP;

    for (int i = t; i < AF * HYP; i += 256) s_wa1[i] = wa1[i];
    for (int i = t; i < EF * HYP; i += 256) s_we1[i] = we1[i];
    for (int i = t; i < NA * AF; i += 256) s_fa[i / AF][i % AF] = fa[b * NA * AF + i];
    for (int i = t; i < NE * EF; i += 256) s_fe[i / EF][i % EF] = fe[b * NE * EF + i];
    __syncthreads();

    for (int i = t; i < NA * HYP; i += 256) {
        int n = i / HYP, k = i % HYP;
        float s = ba1[k];
        #pragma unroll
        for (int f = 0; f < AF; f++) s += s_fa[n][f] * s_wa1[f * HYP + k];
        s_ha[n][k] = fmaxf(s, 0.0f);
    }
    for (int i = t; i < NE * HYP; i += 256) {
        int n = i / HYP, k = i % HYP;
        float s = be1[k];
        #pragma unroll
        for (int f = 0; f < EF; f++) s += s_fe[n][f] * s_we1[f * HYP + k];
        s_he[n][k] = fmaxf(s, 0.0f);
    }
    __syncthreads();

    for (int i = t; i < KA; i += 256) {
        int k = i >> 5, f = i & 31;
        float s = 0.0f;
        #pragma unroll
        for (int n = 0; n < NA; n++) s += s_ha[n][k] * s_fa[n][f];
        store_hilo(g_Ua_hi, g_Ua_lo, rb + i, s);
    }
    if (t < AF) {
        float s = 0.0f;
        #pragma unroll
        for (int n = 0; n < NA; n++) s += s_fa[n][t];
        store_hilo(g_Ua_hi, g_Ua_lo, rb + OFF_FA + t, s);
    }
    for (int i = t; i < KE; i += 256) {
        int k = i / EF, f = i - k * EF;
        float s = 0.0f;
        #pragma unroll
        for (int n = 0; n < NE; n++) s += s_he[n][k] * s_fe[n][f];
        store_hilo(g_Ua_hi, g_Ua_lo, rb + OFF_ME + i, s);
    }
    if (t < EF) {
        float s = 0.0f;
        #pragma unroll
        for (int n = 0; n < NE; n++) s += s_fe[n][t];
        store_hilo(g_Ua_hi, g_Ua_lo, rb + OFF_FE + t, s);
    }
    if (t < (KP - KTOT)) store_hilo(g_Ua_hi, g_Ua_lo, rb + KTOT + t, 0.0f);
}

// ---------------------------------------------------------------------------
// Kernel 3: split-precision bf16 HMMA GEMM (mma.sync.m16n8k16).
// BM=128, BN=64, BK=32 double-buffered via cp.async. 256 threads / 8 warps,
// warp tile 32x32 (2 m-tiles x 4 n-tiles). grid (8, 4, SPLIT) = 256 CTAs.
// Smem (dynamic, 60KB): Ah/Al [2][128][40] bf16, Bh/Bl [2][64][40] bf16.
// ---------------------------------------------------------------------------
#define ASTRIDE 40                       // bf16 elems per row (80 B, 16B-mult)
#define ASZ1    (128 * ASTRIDE * 2)      // bytes per A buffer = 10240
#define BSZ1    (64 * ASTRIDE * 2)       // bytes per B buffer = 5120
#define OFF_AH  0
#define OFF_AL  (2 * ASZ1)
#define OFF_BH  (4 * ASZ1)
#define OFF_BL  (4 * ASZ1 + 2 * BSZ1)
#define SMEM_DYN (4 * ASZ1 + 4 * BSZ1)   // 61440

__global__ void __launch_bounds__(256, 2) gemm_mma() {
    extern __shared__ char dsm[];
    const uint32_t sb = smem_u32(dsm);

    const int t    = threadIdx.x;
    const int lane = t & 31;
    const int wid  = t >> 5;
    const int wm   = (wid & 3) * 32;       // warp m offset within block
    const int wn   = (wid >> 2) * 32;      // warp n offset within block
    const int m0   = blockIdx.x * 128;
    const int n0   = blockIdx.y * 64;
    const int z    = blockIdx.z;
    const int s0   = (NST * z) / SPLIT;
    const int s1   = (NST * (z + 1)) / SPLIT;

    // cp.async per-thread source/dest geometry
    const int am  = t >> 1;                // A row handled twice (q=0,1 -> +0/+64... )
    const int akc = (t & 1) * 2;           // unused split below; recompute per q
    (void)am; (void)akc;

    // ldmatrix per-lane address components (bf16 elems)
    const int a_row = lane & 15;
    const int a_k8  = ((lane >> 4) & 1) * 8;
    const int b_row = (lane & 7) + ((lane >> 4) & 1) * 8;
    const int b_k8  = (lane & 8);          // 0 or 8

    float acc[2][4][4];
    #pragma unroll
    for (int i = 0; i < 2; i++)
        #pragma unroll
        for (int j = 0; j < 4; j++)
            #pragma unroll
            for (int q = 0; q < 4; q++) acc[i][j][q] = 0.0f;

    // stage loader: k0 = stage*32
    auto issue = [&](int s, int buf) {
        const int k0 = s * 32;
        #pragma unroll
        for (int q = 0; q < 2; q++) {
            int idx = t + q * 256;               // [0,512)
            int m = idx >> 2, kc = idx & 3;
            uint32_t doff = (uint32_t)(m * ASTRIDE + kc * 8) * 2;
            const __nv_bfloat16* gh = g_Ua_hi + (size_t)(m0 + m) * KP + k0 + kc * 8;
            const __nv_bfloat16* gl = g_Ua_lo + (size_t)(m0 + m) * KP + k0 + kc * 8;
            cp16(sb + OFF_AH + buf * ASZ1 + doff, gh);
            cp16(sb + OFF_AL + buf * ASZ1 + doff, gl);
        }
        {
            int n = t >> 2, kc = t & 3;
            uint32_t doff = (uint32_t)(n * ASTRIDE + kc * 8) * 2;
            const __nv_bfloat16* gh = g_Wt_hi + (size_t)(n0 + n) * KP + k0 + kc * 8;
            const __nv_bfloat16* gl = g_Wt_lo + (size_t)(n0 + n) * KP + k0 + kc * 8;
            cp16(sb + OFF_BH + buf * BSZ1 + doff, gh);
            cp16(sb + OFF_BL + buf * BSZ1 + doff, gl);
        }
    };

    issue(s0, 0);
    CP_COMMIT();

    int buf = 0;
    for (int s = s0; s < s1; s++) {
        if (s + 1 < s1) {
            issue(s + 1, buf ^ 1);
            CP_COMMIT();
            CP_WAIT(1);
        } else {
            CP_WAIT(0);
        }
        __syncthreads();

        const uint32_t baseAh = sb + OFF_AH + buf * ASZ1;
        const uint32_t baseAl = sb + OFF_AL + buf * ASZ1;
        const uint32_t baseBh = sb + OFF_BH + buf * BSZ1;
        const uint32_t baseBl = sb + OFF_BL + buf * BSZ1;

        #pragma unroll
        for (int kk = 0; kk < 2; kk++) {
            const int kcol = kk * 16;
            uint32_t Ah[2][4], Al[2][4], Bh[4][2], Bl[4][2];
            #pragma unroll
            for (int mt = 0; mt < 2; mt++) {
                uint32_t off = (uint32_t)((wm + mt * 16 + a_row) * ASTRIDE + kcol + a_k8) * 2;
                ldsm4(Ah[mt][0], Ah[mt][1], Ah[mt][2], Ah[mt][3], baseAh + off);
                ldsm4(Al[mt][0], Al[mt][1], Al[mt][2], Al[mt][3], baseAl + off);
            }
            #pragma unroll
            for (int p = 0; p < 2; p++) {
                uint32_t off = (uint32_t)((wn + p * 16 + b_row) * ASTRIDE + kcol + b_k8) * 2;
                ldsm4(Bh[2 * p][0], Bh[2 * p][1], Bh[2 * p + 1][0], Bh[2 * p + 1][1], baseBh + off);
                ldsm4(Bl[2 * p][0], Bl[2 * p][1], Bl[2 * p + 1][0], Bl[2 * p + 1][1], baseBl + off);
            }
            #pragma unroll
            for (int mt = 0; mt < 2; mt++)
                #pragma unroll
                for (int nt = 0; nt < 4; nt++) {
                    mma_bf16(acc[mt][nt], Ah[mt], Bh[nt]);
                    mma_bf16(acc[mt][nt], Ah[mt], Bl[nt]);
                    mma_bf16(acc[mt][nt], Al[mt], Bh[nt]);
                }
        }
        __syncthreads();
        buf ^= 1;
    }

    // epilogue: c0,c1 -> (row, 2col..2col+1), c2,c3 -> (row+8, ...)
    float* P = g_P + (size_t)z * (BATCH * OUTD);
    const int gr  = lane >> 2;
    const int tc2 = (lane & 3) * 2;
    #pragma unroll
    for (int mt = 0; mt < 2; mt++) {
        #pragma unroll
        for (int nt = 0; nt < 4; nt++) {
            int row = m0 + wm + mt * 16 + gr;
            int col = n0 + wn + nt * 8 + tc2;
            float2 v0 = make_float2(acc[mt][nt][0], acc[mt][nt][1]);
            float2 v1 = make_float2(acc[mt][nt][2], acc[mt][nt][3]);
            *(float2*)(P + (size_t)row * OUTD + col)       = v0;
            *(float2*)(P + (size_t)(row + 8) * OUTD + col) = v1;
        }
    }
}

// ---------------------------------------------------------------------------
// Kernel 4: reduce SPLIT partials into d_out.
// ---------------------------------------------------------------------------
__global__ __launch_bounds__(256) void reduce_out(float* __restrict__ out) {
    const int nvec = BATCH * OUTD / 4;
    for (int i = blockIdx.x * blockDim.x + threadIdx.x; i < nvec;
         i += gridDim.x * blockDim.x) {
        float4 s = ((const float4*)g_P)[i];
        #pragma unroll
        for (int zz = 1; zz < SPLIT; zz++) {
            float4 v = ((const float4*)g_P)[(size_t)zz * nvec + i];
            s.x += v.x; s.y += v.y; s.z += v.z; s.w += v.w;
        }
        ((float4*)out)[i] = s;
    }
}

// ---------------------------------------------------------------------------
// Inputs: 0 ally 1 enemy 2 wa1 3 ba1 4 wa2 5 ba2 6 we1 7 be1 8 we2 9 be2
// ---------------------------------------------------------------------------
extern "C" void kernel_launch(void* const* d_in, const int* in_sizes, int n_in,
                              void* d_out, int out_size) {
    const float* fa  = (const float*)d_in[0];
    const float* fe  = (const float*)d_in[1];
    const float* wa1 = (const float*)d_in[2];
    const float* ba1 = (const float*)d_in[3];
    const float* wa2 = (const float*)d_in[4];
    const float* ba2 = (const float*)d_in[5];
    const float* we1 = (const float*)d_in[6];
    const float* be1 = (const float*)d_in[7];
    const float* we2 = (const float*)d_in[8];
    const float* be2 = (const float*)d_in[9];
    float* out = (float*)d_out;

    cudaFuncSetAttribute(gemm_mma, cudaFuncAttributeMaxDynamicSharedMemorySize, SMEM_DYN);

    pack_t<<<dim3(KP / 64, OUTD / 64), 256>>>(wa2, ba2, we2, be2);
    build_u<<<BATCH, 256>>>(fa, fe, wa1, ba1, we1, be1);
    gemm_mma<<<dim3(BATCH / 128, OUTD / 64, SPLIT), 256, SMEM_DYN>>>();
    reduce_out<<<256, 256>>>(out);
}